// round 11
// baseline (speedup 1.0000x reference)
#include <cuda_runtime.h>
#include <cuda_bf16.h>
#include <math_constants.h>

#define BATCH 64
#define SEQ   256
#define TCH   16
#define VOC   262
#define EMB   64
#define HID   32
#define G3    96
#define NSEQ  (BATCH*SEQ)

// Tables (device globals — no allocation allowed)
// Permuted GI rows: pos(gate,j) = gate*32 + tig*8 + hg*2 + e
// r,z entries pre-scaled by 0.5 (sigmoid-via-tanh); bhh folded for r,z.
__device__ __align__(128) float g_GI2[2 * VOC * G3];
// Pre-packed bf16 B fragments (m16n8k16): [dir][nb][kc][lane] = uint2(b0,b1)
// nb<8 rows pre-scaled 0.5.
__device__ uint2 g_WF[2 * 12 * 2 * 32];

__device__ __forceinline__ unsigned packbf(float lo, float hi) {
    unsigned d;
    asm("cvt.rn.bf16x2.f32 %0, %1, %2;" : "=r"(d) : "f"(hi), "f"(lo));
    return d;
}
__device__ __forceinline__ float tanhapx(float x) {
    float r;
    asm("tanh.approx.f32 %0, %1;" : "=f"(r) : "f"(x));
    return r;
}
// MMA with accumulators on four independent float lvalues (in-place)
__device__ __forceinline__ void mma4(float& d0, float& d1, float& d2, float& d3,
                                     const unsigned* a, unsigned b0, unsigned b1) {
    asm("mma.sync.aligned.m16n8k16.row.col.f32.bf16.bf16.f32 "
        "{%0,%1,%2,%3}, {%4,%5,%6,%7}, {%8,%9}, {%0,%1,%2,%3};"
        : "+f"(d0), "+f"(d1), "+f"(d2), "+f"(d3)
        : "r"(a[0]), "r"(a[1]), "r"(a[2]), "r"(a[3]), "r"(b0), "r"(b1));
}
__device__ __forceinline__ float& f4c(float4& v, int c) {
    return c == 0 ? v.x : c == 1 ? v.y : c == 2 ? v.z : v.w;
}

// ---------------------------------------------------------------------------
// Kernel 1: GI tables + bf16 B-fragment pack. grid = VOC+1, block = 192.
// ---------------------------------------------------------------------------
__global__ void build_tables(const float* __restrict__ emb,
                             const float* __restrict__ Wih_f,
                             const float* __restrict__ bih_f,
                             const float* __restrict__ bhh_f,
                             const float* __restrict__ Wih_b,
                             const float* __restrict__ bih_b,
                             const float* __restrict__ bhh_b,
                             const float* __restrict__ Whh_f,
                             const float* __restrict__ Whh_b) {
    int c   = blockIdx.x;
    int tid = threadIdx.x;
    if (c < VOC) {
        int dir = tid / 96;
        int g   = tid % 96;
        __shared__ float e[EMB];
        if (tid < EMB) e[tid] = emb[c * EMB + tid];
        __syncthreads();
        const float* Wih = dir ? Wih_b : Wih_f;
        const float* bih = dir ? bih_b : bih_f;
        const float* bhh = dir ? bhh_b : bhh_f;
        float a0 = bih[g] + (g < 64 ? bhh[g] : 0.0f);
        float a1 = 0.0f;
        const float4* wr4 = (const float4*)(Wih + g * EMB);
        #pragma unroll
        for (int k4 = 0; k4 < EMB / 4; k4++) {
            float4 wv = wr4[k4];
            a0 = fmaf(wv.x, e[4 * k4],     a0);
            a1 = fmaf(wv.y, e[4 * k4 + 1], a1);
            a0 = fmaf(wv.z, e[4 * k4 + 2], a0);
            a1 = fmaf(wv.w, e[4 * k4 + 3], a1);
        }
        float v = a0 + a1;
        if (g < 64) v *= 0.5f;               // sigmoid-via-tanh prescale
        int gate = g >> 5, j = g & 31;
        int hg = j >> 3, tg = (j >> 1) & 3, eb = j & 1;
        int pos = gate * 32 + tg * 8 + hg * 2 + eb;
        g_GI2[dir * (VOC * G3) + c * G3 + pos] = v;
    } else {
        for (int i = tid; i < 1536; i += 192) {
            int d    = i / 768;
            int rem  = i % 768;
            int nb   = rem / 64;
            int kc   = (rem / 32) & 1;
            int lane = rem & 31;
            int gid = lane >> 2, tg = lane & 3;
            const float* W = d ? Whh_b : Whh_f;
            const float* row = W + (8 * nb + gid) * HID;
            float s = (nb < 8) ? 0.5f : 1.0f;    // r,z rows prescaled
            int k0 = 16 * kc + 2 * tg;
            g_WF[i] = make_uint2(packbf(s * row[k0],     s * row[k0 + 1]),
                                 packbf(s * row[k0 + 8], s * row[k0 + 9]));
        }
    }
}

// Load one step's gi (12 float4 = 48 floats) for chars cA (rows 0-7) / cB (8-15)
__device__ __forceinline__ void load_gi(float4* dst, const float* __restrict__ GI,
                                        int cA, int cB, int tig) {
    const float4* pA4 = (const float4*)(GI + cA * G3);
    const float4* pB4 = (const float4*)(GI + cB * G3);
    dst[0]  = pA4[tig * 2];      dst[1]  = pA4[tig * 2 + 1];
    dst[2]  = pA4[8 + tig * 2];  dst[3]  = pA4[8 + tig * 2 + 1];
    dst[4]  = pA4[16 + tig * 2]; dst[5]  = pA4[16 + tig * 2 + 1];
    dst[6]  = pB4[tig * 2];      dst[7]  = pB4[tig * 2 + 1];
    dst[8]  = pB4[8 + tig * 2];  dst[9]  = pB4[8 + tig * 2 + 1];
    dst[10] = pB4[16 + tig * 2]; dst[11] = pB4[16 + tig * 2 + 1];
}

// One GRU step: consume cur (in-place accumulate), prefetch next into nxt.
__device__ __forceinline__ void gru_step(
    float4* cur, float4* nxt,
    const float* __restrict__ GI, int cAn, int cBn, int tig,
    const uint2* s_bf, int lane,
    const float* bnlo, const float* bnhi,
    float hn[4][4], float hmax[4][4])
{
    // prefetch gi for next step (consumed one full step later)
    load_gi(nxt, GI, cAn, cBn, tig);

    // pack A fragments (lane-local)
    unsigned a[2][4];
    #pragma unroll
    for (int kc = 0; kc < 2; kc++) {
        a[kc][0] = packbf(hn[2 * kc][0],     hn[2 * kc][1]);
        a[kc][1] = packbf(hn[2 * kc][2],     hn[2 * kc][3]);
        a[kc][2] = packbf(hn[2 * kc + 1][0], hn[2 * kc + 1][1]);
        a[kc][3] = packbf(hn[2 * kc + 1][2], hn[2 * kc + 1][3]);
    }

    // n-gate accumulators start at recurrent bias
    float nacc[4][4];
    #pragma unroll
    for (int hg = 0; hg < 4; hg++) {
        nacc[hg][0] = bnlo[hg]; nacc[hg][1] = bnhi[hg];
        nacc[hg][2] = bnlo[hg]; nacc[hg][3] = bnhi[hg];
    }

    // 24 MMAs: r,z accumulate IN-PLACE into cur; n into nacc
    #pragma unroll
    for (int kc = 0; kc < 2; kc++) {
        #pragma unroll
        for (int m = 0; m < 4; m++) {
            int bi = m >> 1;
            int c0 = (m & 1) * 2;
            uint2 br = s_bf[(m * 2 + kc) * 32 + lane];
            mma4(f4c(cur[bi], c0),     f4c(cur[bi], c0 + 1),
                 f4c(cur[6 + bi], c0), f4c(cur[6 + bi], c0 + 1),
                 a[kc], br.x, br.y);
            uint2 bz = s_bf[((4 + m) * 2 + kc) * 32 + lane];
            mma4(f4c(cur[2 + bi], c0),     f4c(cur[2 + bi], c0 + 1),
                 f4c(cur[8 + bi], c0),     f4c(cur[8 + bi], c0 + 1),
                 a[kc], bz.x, bz.y);
            uint2 bnf = s_bf[((8 + m) * 2 + kc) * 32 + lane];
            mma4(nacc[m][0], nacc[m][1], nacc[m][2], nacc[m][3],
                 a[kc], bnf.x, bnf.y);
        }
    }

    // activations read gate pre-activations directly from cur
    #pragma unroll
    for (int hg = 0; hg < 4; hg++)
        #pragma unroll
        for (int s = 0; s < 4; s++) {
            int bi = (s >> 1) * 6 + (hg >> 1);
            int c  = (hg & 1) * 2 + (s & 1);
            float r = fmaf(tanhapx(f4c(cur[bi], c)),     0.5f, 0.5f);
            float z = fmaf(tanhapx(f4c(cur[2 + bi], c)), 0.5f, 0.5f);
            float n = tanhapx(fmaf(r, nacc[hg][s], f4c(cur[4 + bi], c)));
            float h = fmaf(z, hn[hg][s] - n, n);
            hn[hg][s] = h;
            hmax[hg][s] = fmaxf(hmax[hg][s], h);
        }
}

// ---------------------------------------------------------------------------
// Kernel 2: bf16 tensor-core GRU. 512 blocks x 64 thr (2 warps), 6 blocks/SM
// (single wave, 12 warps/SM). One warp = 16 seqs x 2 serial tasks, one dir.
// In-place MMA accumulators, ping-pong gi prefetch, B fragments in smem.
// ---------------------------------------------------------------------------
__global__ __launch_bounds__(64, 6)
void gru_mma(const int* __restrict__ x,
             const float* __restrict__ bhh_f,
             const float* __restrict__ bhh_b,
             float* __restrict__ out) {
    __shared__ uint2 s_bf[12 * 2 * 32];     // 6 KB B fragments (dir-uniform)

    int tid  = threadIdx.x;
    int wb   = tid >> 5;
    int lane = tid & 31;
    int gid  = lane >> 2;
    int tig  = lane & 3;
    int dir  = blockIdx.x >> 8;                 // block-uniform
    int wi   = (blockIdx.x & 255) * 2 + wb;     // 0..511

    {
        const uint2* src = g_WF + dir * 768;
        #pragma unroll
        for (int i = 0; i < 12; i++)
            s_bf[tid + 64 * i] = src[tid + 64 * i];
    }
    __syncthreads();

    const float* __restrict__ GI  = g_GI2 + dir * (VOC * G3);
    const float* __restrict__ bhh = dir ? bhh_b : bhh_f;

    float bnlo[4], bnhi[4];
    #pragma unroll
    for (int hg = 0; hg < 4; hg++) {
        bnlo[hg] = bhh[64 + 8 * hg + 2 * tig];
        bnhi[hg] = bhh[64 + 8 * hg + 2 * tig + 1];
    }

    #pragma unroll 1
    for (int task = 0; task < 2; task++) {
        int seq0 = (wi + task * 512) << 4;
        const int* xA = x + (seq0 + gid) * TCH;
        const int* xB = x + (seq0 + gid + 8) * TCH;

        float hn[4][4], hmax[4][4];
        #pragma unroll
        for (int hg = 0; hg < 4; hg++)
            #pragma unroll
            for (int s = 0; s < 4; s++) { hn[hg][s] = 0.0f; hmax[hg][s] = -CUDART_INF_F; }

        float4 buf0[12], buf1[12];

        // T(k) = dir ? 15-k : k  (masked to stay in-bounds on overrun)
        #define TIDX(k) (dir ? ((TCH - 1 - (k)) & (TCH - 1)) : ((k) & (TCH - 1)))

        load_gi(buf0, GI, xA[TIDX(0)], xB[TIDX(0)], tig);
        int cA1 = xA[TIDX(1)], cB1 = xB[TIDX(1)];

        #pragma unroll 1
        for (int it = 0; it < 8; ++it) {
            int tt = 2 * it;
            int cA2 = xA[TIDX(tt + 2)], cB2 = xB[TIDX(tt + 2)];
            // step tt: consume buf0, prefetch T(tt+1) into buf1
            gru_step(buf0, buf1, GI, cA1, cB1, tig, s_bf, lane, bnlo, bnhi, hn, hmax);
            cA1 = xA[TIDX(tt + 3)]; cB1 = xB[TIDX(tt + 3)];
            // step tt+1: consume buf1, prefetch T(tt+2) into buf0
            gru_step(buf1, buf0, GI, cA2, cB2, tig, s_bf, lane, bnlo, bnhi, hn, hmax);
        }
        #undef TIDX

        int sA = seq0 + gid, sB = seq0 + gid + 8;
        #pragma unroll
        for (int hg = 0; hg < 4; hg++) {
            int col = 8 * hg + 2 * tig;
            *(float2*)(out + sA * 64 + dir * 32 + col) = make_float2(hmax[hg][0], hmax[hg][1]);
            *(float2*)(out + sB * 64 + dir * 32 + col) = make_float2(hmax[hg][2], hmax[hg][3]);
        }
    }
}

// ---------------------------------------------------------------------------
// kernel_launch
// ---------------------------------------------------------------------------
extern "C" void kernel_launch(void* const* d_in, const int* in_sizes, int n_in,
                              void* d_out, int out_size) {
    const int*   x     = (const int*)  d_in[0];
    const float* emb   = (const float*)d_in[1];
    const float* Wih_f = (const float*)d_in[2];
    const float* Whh_f = (const float*)d_in[3];
    const float* bih_f = (const float*)d_in[4];
    const float* bhh_f = (const float*)d_in[5];
    const float* Wih_b = (const float*)d_in[6];
    const float* Whh_b = (const float*)d_in[7];
    const float* bih_b = (const float*)d_in[8];
    const float* bhh_b = (const float*)d_in[9];
    float* out = (float*)d_out;

    build_tables<<<VOC + 1, 192>>>(emb, Wih_f, bih_f, bhh_f,
                                   Wih_b, bih_b, bhh_b, Whh_f, Whh_b);

    // 512 blocks x 2 warps = 1024 warps x 2 serial tasks. 6 blocks/SM,
    // single wave. Blocks 0..255 dir0, 256..511 dir1.
    gru_mma<<<512, 64>>>(x, bhh_f, bhh_b, out);
}